// round 15
// baseline (speedup 1.0000x reference)
#include <cuda_runtime.h>
#include <cstdint>
#include <math.h>

#define CS     16
#define NG     192
#define P      196               // row pitch (2 guard + 192 + 2 guard)
#define FROWS  12                // rows per CTA per batch
#define NTHR   768               // two independent 384-thread halves (2 batches)
#define TSTEPS 256
#define NBLK   (TSTEPS / 2)
#define TXBYTES 1536             // 192 cols x 2 rows x 4B per side per block per half
#define BUF    (FROWS * P)
#define HHALF  (2 * 2 * 2 * P)   // halo floats per half: [parity][side][idx][P]
#define DYNF   (6 * BUF + 2 * HHALF + 2 * TSTEPS + 8)

typedef unsigned long long ull;

__device__ __forceinline__ uint32_t s2u(const void* p) {
    return (uint32_t)__cvta_generic_to_shared((void*)p);
}
__device__ __forceinline__ uint32_t mapa_u32(uint32_t a, uint32_t r) {
    uint32_t d;
    asm("mapa.shared::cluster.u32 %0, %1, %2;" : "=r"(d) : "r"(a), "r"(r));
    return d;
}
__device__ __forceinline__ void st_async_f32(uint32_t raddr, float v, uint32_t rmbar) {
    asm volatile("st.async.shared::cluster.mbarrier::complete_tx::bytes.b32 [%0], %1, [%2];"
                 :: "r"(raddr), "r"(__float_as_uint(v)), "r"(rmbar) : "memory");
}
__device__ __forceinline__ void mbar_init(uint32_t a, uint32_t cnt) {
    asm volatile("mbarrier.init.shared.b64 [%0], %1;" :: "r"(a), "r"(cnt) : "memory");
}
__device__ __forceinline__ void mbar_expect_tx(uint32_t a, uint32_t bytes) {
    asm volatile("mbarrier.arrive.expect_tx.shared.b64 _, [%0], %1;"
                 :: "r"(a), "r"(bytes) : "memory");
}
__device__ __forceinline__ void mbar_wait(uint32_t addr, uint32_t parity) {
    asm volatile(
        "{\n\t"
        ".reg .pred P;\n\t"
        "WL_%=:\n\t"
        "mbarrier.try_wait.parity.acquire.cta.shared::cta.b64 P, [%0], %1, 0x989680;\n\t"
        "@P bra.uni WD_%=;\n\t"
        "bra.uni WL_%=;\n\t"
        "WD_%=:\n\t"
        "}"
        :: "r"(addr), "r"(parity) : "memory");
}
__device__ __forceinline__ void cl_arrive() {
    asm volatile("barrier.cluster.arrive.aligned;" ::: "memory");
}
__device__ __forceinline__ void cl_wait() {
    asm volatile("barrier.cluster.wait.aligned;" ::: "memory");
}
__device__ __forceinline__ void rgrp_bar(int id) {
    asm volatile("bar.sync %0, %1;" :: "r"(id), "r"(192) : "memory");
}

__device__ __forceinline__ float pml1(int i) {
    int d;
    if (i <= 20)           d = 20 - i;
    else if (i >= NG - 21) d = i - (NG - 21);
    else return 0.0f;
    double t = (double)d * 0.05;
    double t2 = t * t;
    return (float)(3.0 * t2 * t2);
}

__global__ void __launch_bounds__(NTHR, 1)
wave_kernel(const float* __restrict__ x, const float* __restrict__ rho,
            float* __restrict__ out)
{
    extern __shared__ float dsm[];
    __shared__ alignas(8) ull mbarT[2][2], mbarB[2][2];   // [half][parity]

    const int tid   = threadIdx.x;
    const int col   = tid % NG;
    const int half  = tid / 384;              // which batch of the pair
    const int rgrp2 = (tid / NG) & 1;         // 0: rows 0..5 (+ext -1), 1: rows 6..11 (+ext 12)
    const int rank  = blockIdx.x % CS;
    const int bbase = (blockIdx.x / CS) * 2;  // first batch of this cluster

    // dynamic smem carve
    float* bA   = dsm + (0 * 2 + half) * BUF;
    float* bB   = dsm + (2 * 2 + half) * BUF - 2 * BUF;   // = dsm + (2+half)*BUF
    float* bC   = dsm + (4 + half) * BUF;
    bB = dsm + (2 + half) * BUF;
    float* hbase = dsm + 6 * BUF + half * HHALF;          // [parity][side][idx][P]
    float* xsAll = dsm + 6 * BUF + 2 * HHALF;             // [2][TSTEPS]
    float* xs    = xsAll + half * TSTEPS;
    float* pbuf  = xsAll + 2 * TSTEPS;                    // [2][3]

    for (int i = tid; i < DYNF; i += NTHR) dsm[i] = 0.f;
    __syncthreads();   // zeros before xs load (same region writers differ)
    for (int i = tid; i < 2 * TSTEPS; i += NTHR)
        xsAll[i] = x[(bbase + i / TSTEPS) * TSTEPS + (i % TSTEPS)];

    const bool topR = (rgrp2 == 0);
    const bool hasExt = topR ? (rank > 0) : (rank < CS - 1);

    if (tid == 0) {
#pragma unroll
        for (int h = 0; h < 2; ++h)
#pragma unroll
            for (int p = 0; p < 2; ++p) {
                mbar_init(s2u(&mbarT[h][p]), 1);
                mbar_init(s2u(&mbarB[h][p]), 1);
                if (rank > 0)      mbar_expect_tx(s2u(&mbarT[h][p]), TXBYTES);
                if (rank < CS - 1) mbar_expect_tx(s2u(&mbarB[h][p]), TXBYTES);
            }
    }

    // ---- coefficients for 8 stencil rows: j=0..7 <-> local row 6*rgrp2 + j - 1 ----
    const float HM2 = (float)(1.0 / (2.01 * 2.01));
    float Qp[8], Qm[8], Rc[8];
    float cur[8], prev[8], v[8];
#pragma unroll
    for (int j = 0; j < 8; ++j) {
        int g = rank * FROWS + rgrp2 * 6 + j - 1;
        int gc = min(max(g, 0), NG - 1);
        float cc = rho[gc * NG + col];
        float nn = (gc > 0)      ? rho[(gc - 1) * NG + col] : 0.f;
        float ss = (gc < NG - 1) ? rho[(gc + 1) * NG + col] : 0.f;
        float ww = (col > 0)     ? rho[gc * NG + col - 1]   : 0.f;
        float ee = (col < NG-1)  ? rho[gc * NG + col + 1]   : 0.f;
        float lpf = 0.5f * cc + 0.125f * (nn + ss + ww + ee);
        float pr  = (1.0f + tanhf(100.0f * (lpf - 0.5f))) * 0.5f;
        float c   = 1.0f - 0.1f * pr;
        float bx = pml1(gc), by = pml1(col);
        float bb = sqrtf(bx * bx + by * by);
        float A1 = 1.0f / (1.0f + 0.5f * bb);
        float Q  = A1 * (1.0f - 0.5f * bb);
        float R  = A1 * (c * c) * HM2;
        Qp[j] = 1.0f + Q - 4.0f * R;
        Qm[j] = Q;
        Rc[j] = R;
        cur[j] = 0.f; prev[j] = 0.f; v[j] = 0.f;
    }

    const int side = topR ? 0 : 1;
    const float* ph1[2]; const float* ph0[2];
#pragma unroll
    for (int p = 0; p < 2; ++p) {
        ph1[p] = hbase + ((p * 2 + side) * 2 + 0) * P + col + 2;   // y(t) row ∓1
        ph0[p] = hbase + ((p * 2 + side) * 2 + 1) * P + col + 2;   // y(t) row ∓2
    }
    uint32_t pa1[2] = {0,0}, pa0[2] = {0,0}, rmb[2] = {0,0};
    if (hasExt) {
        int nr = topR ? rank - 1 : rank + 1;
        int ts = topR ? 1 : 0;
#pragma unroll
        for (int p = 0; p < 2; ++p) {
            pa1[p] = mapa_u32(s2u(hbase + ((p * 2 + ts) * 2 + 0) * P + col + 2), (uint32_t)nr);
            pa0[p] = mapa_u32(s2u(hbase + ((p * 2 + ts) * 2 + 1) * P + col + 2), (uint32_t)nr);
            rmb[p] = mapa_u32(s2u(topR ? &mbarB[half][p] : &mbarT[half][p]), (uint32_t)nr);
        }
    }
    const uint32_t mbOwn[2] = { s2u(topR ? &mbarT[half][0] : &mbarB[half][0]),
                                s2u(topR ? &mbarT[half][1] : &mbarB[half][1]) };

    const int ofs = rgrp2 * 6 * P + col + 2;
    float* pr_ = bA + ofs;    // y(t)
    float* pm_ = bB + ofs;    // y(t+1)
    float* po_ = bC + ofs;    // y(t+2)

    // Source (40,96): rank3 rgrp0 j=5. Probes (160,{48,96,144}): rank13 rgrp0 j=5.
    const bool isSrc = (rank == 3)  && topR && (col == 96);
    const bool isPrb = (rank == 13) && topR &&
                       ((col == 48) | (col == 96) | (col == 144));
    float pacc = 0.f;

    cl_arrive(); cl_wait();   // zeros + mbar init/expects visible cluster-wide

    for (int b = 0; b < NBLK; ++b) {
        const int hp = b & 1, hq = hp ^ 1;
        const float xs1 = xs[2 * b];
        const float xs2 = xs[2 * b + 1];

        if (hasExt && b > 0) {
            mbar_wait(mbOwn[hp], (uint32_t)(((b - 1) >> 1) & 1));
            if (col == 0) mbar_expect_tx(mbOwn[hp], TXBYTES);
        }

        // ============ step 1: t -> t+1 =============
        float cw[8], ce[8], c0n, s7;
        if (topR) {
            const float* h1c = ph1[hp];
            cur[0] = h1c[0];
            c0n    = ph0[hp][0];
            cw[0]  = h1c[-1]; ce[0] = h1c[1];
            cur[7] = pr_[6 * P];
            s7     = pr_[7 * P];
            cw[7]  = pr_[6 * P - 1]; ce[7] = pr_[6 * P + 1];
        } else {
            cur[0] = pr_[-P];
            c0n    = pr_[-2 * P];
            cw[0]  = pr_[-P - 1]; ce[0] = pr_[-P + 1];
            const float* h1c = ph1[hp];
            cur[7] = h1c[0];
            s7     = ph0[hp][0];
            cw[7]  = h1c[-1]; ce[7] = h1c[1];
        }
#pragma unroll
        for (int j = 1; j < 7; ++j) {
            cw[j] = pr_[(j - 1) * P - 1];
            ce[j] = pr_[(j - 1) * P + 1];
        }

        v[0] = fmaf(Qp[0], cur[0],
               fmaf(-Qm[0], prev[0], Rc[0] * ((c0n + cur[1]) + (cw[0] + ce[0]))));
        if (topR && !hasExt) v[0] = 0.f;
#pragma unroll
        for (int j = 1; j < 7; ++j) {
            float yn = fmaf(Qp[j], cur[j],
                       fmaf(-Qm[j], prev[j], Rc[j] * ((cur[j - 1] + cur[j + 1]) + (cw[j] + ce[j]))));
            if (j == 5) {
                if (isSrc) yn += xs1;
                if (isPrb) pacc = fmaf(yn, yn, pacc);
            }
            v[j] = yn;
            pm_[(j - 1) * P] = yn;
        }
        v[7] = fmaf(Qp[7], cur[7],
               fmaf(-Qm[7], prev[7], Rc[7] * ((cur[6] + s7) + (cw[7] + ce[7]))));
        if (!topR && !hasExt) v[7] = 0.f;

        rgrp_bar(1 + (tid / 192));   // per-rgrp ordering of pm writes

        // ============ step 2: t+1 -> t+2, own rows j=1..6 ============
        float w2[7], e2[7];
#pragma unroll
        for (int j = 1; j < 7; ++j) {
            w2[j] = pm_[(j - 1) * P - 1];
            e2[j] = pm_[(j - 1) * P + 1];
        }
        auto s2 = [&](int j) -> float {
            float yn = fmaf(Qp[j], v[j],
                       fmaf(-Qm[j], cur[j], Rc[j] * ((v[j - 1] + v[j + 1]) + (w2[j] + e2[j]))));
            if (j == 5) {
                if (isSrc) yn += xs2;
                if (isPrb) pacc = fmaf(yn, yn, pacc);
            }
            po_[(j - 1) * P] = yn;
            prev[j] = v[j];
            cur[j]  = yn;
            return yn;
        };

        if (topR) {
            float a0 = s2(1), a1 = s2(2);
            if (hasExt) {
                st_async_f32(pa1[hq], a0, rmb[hq]);
                st_async_f32(pa0[hq], a1, rmb[hq]);
            }
        } else {
            float a0 = s2(6), a1 = s2(5);
            if (hasExt) {
                st_async_f32(pa1[hq], a0, rmb[hq]);
                st_async_f32(pa0[hq], a1, rmb[hq]);
            }
        }

        if (topR) { s2(3); s2(4); s2(5); s2(6); }
        else      { s2(4); s2(3); s2(2); s2(1); }
        prev[0] = v[0]; prev[7] = v[7];

        __syncthreads();

        float* t0 = pr_; pr_ = po_; po_ = pm_; pm_ = t0;
    }

    cl_arrive(); cl_wait();   // quiesce in-flight async stores before exit

    if (isPrb) pbuf[half * 3 + (col - 48) / 48] = pacc;
    __syncthreads();
    if (rank == 13 && (tid % 384) == 0) {
        float a = pbuf[half * 3 + 0], b = pbuf[half * 3 + 1], c = pbuf[half * 3 + 2];
        float s = a + b + c;
        out[(bbase + half) * 3 + 0] = a / s;
        out[(bbase + half) * 3 + 1] = b / s;
        out[(bbase + half) * 3 + 2] = c / s;
    }
}

extern "C" void kernel_launch(void* const* d_in, const int* in_sizes, int n_in,
                              void* d_out, int out_size)
{
    (void)in_sizes; (void)n_in; (void)out_size;
    const float* x   = (const float*)d_in[0];   // (4,256) f32
    const float* rho = (const float*)d_in[1];   // (192,192) f32
    float* out = (float*)d_out;                 // (4,3) f32

    cudaFuncSetAttribute(wave_kernel,
                         cudaFuncAttributeNonPortableClusterSizeAllowed, 1);
    cudaFuncSetAttribute(wave_kernel,
                         cudaFuncAttributeMaxDynamicSharedMemorySize,
                         DYNF * (int)sizeof(float));

    cudaLaunchConfig_t cfg = {};
    cfg.gridDim  = dim3(CS * 2, 1, 1);           // 2 clusters x 16 CTAs (2 batches/CTA)
    cfg.blockDim = dim3(NTHR, 1, 1);
    cfg.dynamicSmemBytes = DYNF * sizeof(float);
    cudaLaunchAttribute attrs[1];
    attrs[0].id = cudaLaunchAttributeClusterDimension;
    attrs[0].val.clusterDim = {CS, 1, 1};
    cfg.attrs = attrs;
    cfg.numAttrs = 1;
    cudaLaunchKernelEx(&cfg, wave_kernel, x, rho, out);
}

// round 16
// speedup vs baseline: 1.9077x; 1.9077x over previous
#include <cuda_runtime.h>
#include <cstdint>
#include <math.h>

#define CS     16
#define NG     192
#define P      196               // row pitch (2 guard + 192 + 2 guard)
#define FROWS  12                // rows per CTA
#define NTHR   768               // 4 rgrps x 192 threads, 3 own rows each
#define TSTEPS 256
#define NBLK   (TSTEPS / 2)
#define TXBYTES 1536             // 192 cols x 2 rows x 4B per side per block

typedef unsigned long long ull;

__device__ __forceinline__ uint32_t s2u(const void* p) {
    return (uint32_t)__cvta_generic_to_shared((void*)p);
}
__device__ __forceinline__ uint32_t mapa_u32(uint32_t a, uint32_t r) {
    uint32_t d;
    asm("mapa.shared::cluster.u32 %0, %1, %2;" : "=r"(d) : "r"(a), "r"(r));
    return d;
}
__device__ __forceinline__ void st_async_f32(uint32_t raddr, float v, uint32_t rmbar) {
    asm volatile("st.async.shared::cluster.mbarrier::complete_tx::bytes.b32 [%0], %1, [%2];"
                 :: "r"(raddr), "r"(__float_as_uint(v)), "r"(rmbar) : "memory");
}
__device__ __forceinline__ void mbar_init(uint32_t a, uint32_t cnt) {
    asm volatile("mbarrier.init.shared.b64 [%0], %1;" :: "r"(a), "r"(cnt) : "memory");
}
__device__ __forceinline__ void mbar_expect_tx(uint32_t a, uint32_t bytes) {
    asm volatile("mbarrier.arrive.expect_tx.shared.b64 _, [%0], %1;"
                 :: "r"(a), "r"(bytes) : "memory");
}
__device__ __forceinline__ void mbar_wait(uint32_t addr, uint32_t parity) {
    asm volatile(
        "{\n\t"
        ".reg .pred P;\n\t"
        "WL_%=:\n\t"
        "mbarrier.try_wait.parity.acquire.cta.shared::cta.b64 P, [%0], %1, 0x989680;\n\t"
        "@P bra.uni WD_%=;\n\t"
        "bra.uni WL_%=;\n\t"
        "WD_%=:\n\t"
        "}"
        :: "r"(addr), "r"(parity) : "memory");
}
__device__ __forceinline__ void cl_arrive() {
    asm volatile("barrier.cluster.arrive.aligned;" ::: "memory");
}
__device__ __forceinline__ void cl_wait() {
    asm volatile("barrier.cluster.wait.aligned;" ::: "memory");
}
__device__ __forceinline__ void rgrp_bar(int id) {
    asm volatile("bar.sync %0, %1;" :: "r"(id), "r"(192) : "memory");
}

__device__ __forceinline__ float pml1(int i) {
    int d;
    if (i <= 20)           d = 20 - i;
    else if (i >= NG - 21) d = i - (NG - 21);
    else return 0.0f;
    double t = (double)d * 0.05;
    double t2 = t * t;
    return (float)(3.0 * t2 * t2);
}

__global__ void __launch_bounds__(NTHR, 1)
wave_kernel(const float* __restrict__ x, const float* __restrict__ rho,
            float* __restrict__ out)
{
    __shared__ float bufA[FROWS * P], bufB[FROWS * P], bufC[FROWS * P];
    __shared__ float halo[2][2][2][P];   // [parity][side 0=top,1=bot][0=row∓1,1=row∓2][P]
    __shared__ float xs[TSTEPS];
    __shared__ float pbuf[3];
    __shared__ alignas(8) ull mbarT[2], mbarB[2];

    const int tid   = threadIdx.x;
    const int col   = tid % NG;
    const int rgrp  = tid / NG;           // 0..3, owns rows 3*rgrp .. 3*rgrp+2
    const int rank  = blockIdx.x % CS;
    const int batch = blockIdx.x / CS;

    for (int i = tid; i < FROWS * P; i += NTHR) { bufA[i] = 0.f; bufB[i] = 0.f; bufC[i] = 0.f; }
    for (int i = tid; i < 2*2*2*P; i += NTHR) (&halo[0][0][0][0])[i] = 0.f;
    for (int i = tid; i < TSTEPS; i += NTHR) xs[i] = x[batch * TSTEPS + i];

    const bool topR = (rgrp == 0), botR = (rgrp == 3);
    const bool hasExt = topR ? (rank > 0) : (botR ? (rank < CS - 1) : false);

    if (tid == 0) {
#pragma unroll
        for (int p = 0; p < 2; ++p) {
            mbar_init(s2u(&mbarT[p]), 1);
            mbar_init(s2u(&mbarB[p]), 1);
            if (rank > 0)      mbar_expect_tx(s2u(&mbarT[p]), TXBYTES);
            if (rank < CS - 1) mbar_expect_tx(s2u(&mbarB[p]), TXBYTES);
        }
    }

    // ---- coefficients for 5 stencil rows: j=0..4 <-> local row 3*rgrp + j - 1 ----
    const float HM2 = (float)(1.0 / (2.01 * 2.01));
    float Qp[5], Qm[5], Rc[5];
    float cur[5], prev[5], v[5];
#pragma unroll
    for (int j = 0; j < 5; ++j) {
        int g = rank * FROWS + rgrp * 3 + j - 1;
        int gc = min(max(g, 0), NG - 1);
        float cc = rho[gc * NG + col];
        float nn = (gc > 0)      ? rho[(gc - 1) * NG + col] : 0.f;
        float ss = (gc < NG - 1) ? rho[(gc + 1) * NG + col] : 0.f;
        float ww = (col > 0)     ? rho[gc * NG + col - 1]   : 0.f;
        float ee = (col < NG-1)  ? rho[gc * NG + col + 1]   : 0.f;
        float lpf = 0.5f * cc + 0.125f * (nn + ss + ww + ee);
        float pr  = (1.0f + tanhf(100.0f * (lpf - 0.5f))) * 0.5f;
        float c   = 1.0f - 0.1f * pr;
        float bx = pml1(gc), by = pml1(col);
        float bb = sqrtf(bx * bx + by * by);
        float A1 = 1.0f / (1.0f + 0.5f * bb);
        float Q  = A1 * (1.0f - 0.5f * bb);
        float R  = A1 * (c * c) * HM2;
        Qp[j] = 1.0f + Q - 4.0f * R;
        Qm[j] = Q;
        Rc[j] = R;
        cur[j] = 0.f; prev[j] = 0.f; v[j] = 0.f;
    }

    const int side = topR ? 0 : 1;               // used only by rgrp0/rgrp3
    const float* ph1[2]; const float* ph0[2];
#pragma unroll
    for (int p = 0; p < 2; ++p) {
        ph1[p] = &halo[p][side][0][col + 2];     // y(t) row ∓1
        ph0[p] = &halo[p][side][1][col + 2];     // y(t) row ∓2
    }
    uint32_t pa1[2] = {0,0}, pa0[2] = {0,0}, rmb[2] = {0,0};
    if (hasExt) {
        int nr = topR ? rank - 1 : rank + 1;
        int ts = topR ? 1 : 0;
#pragma unroll
        for (int p = 0; p < 2; ++p) {
            pa1[p] = mapa_u32(s2u(&halo[p][ts][0][col + 2]), (uint32_t)nr);
            pa0[p] = mapa_u32(s2u(&halo[p][ts][1][col + 2]), (uint32_t)nr);
            rmb[p] = mapa_u32(s2u(topR ? &mbarB[p] : &mbarT[p]), (uint32_t)nr);
        }
    }
    const uint32_t mbOwn[2] = { s2u(topR ? &mbarT[0] : &mbarB[0]),
                                s2u(topR ? &mbarT[1] : &mbarB[1]) };

    const int ofs = rgrp * 3 * P + col + 2;      // own row 0 (local row 3*rgrp)
    float* pr_ = bufA + ofs;    // y(t)
    float* pm_ = bufB + ofs;    // y(t+1)
    float* po_ = bufC + ofs;    // y(t+2)

    // Source (40,96): rank3 local row 4 -> rgrp1 j=2. Probes (160,*): rank13 rgrp1 j=2.
    const bool isSrc = (rank == 3)  && (rgrp == 1) && (col == 96);
    const bool isPrb = (rank == 13) && (rgrp == 1) &&
                       ((col == 48) | (col == 96) | (col == 144));
    float pacc = 0.f;

    cl_arrive(); cl_wait();   // zeros + mbar init/expects visible cluster-wide

    for (int b = 0; b < NBLK; ++b) {
        const int hp = b & 1, hq = hp ^ 1;
        const float xs1 = xs[2 * b];
        const float xs2 = xs[2 * b + 1];

        if (hasExt && b > 0) {
            mbar_wait(mbOwn[hp], (uint32_t)(((b - 1) >> 1) & 1));
            if (col == 0) mbar_expect_tx(mbOwn[hp], TXBYTES);
        }

        // ============ step 1: t -> t+1, rows j=0..4 ============
        float cw[5], ce[5], c0n, s4;
        if (topR) {
            const float* h1c = ph1[hp];
            cur[0] = h1c[0];                 // y(t) row -1 (halo)
            c0n    = ph0[hp][0];             // y(t) row -2
            cw[0]  = h1c[-1]; ce[0] = h1c[1];
            cur[4] = pr_[3 * P];             // seam row 3
            s4     = pr_[4 * P];             // row 4
            cw[4]  = pr_[3 * P - 1]; ce[4] = pr_[3 * P + 1];
        } else if (botR) {
            cur[0] = pr_[-P];                // seam row 8
            c0n    = pr_[-2 * P];            // row 7
            cw[0]  = pr_[-P - 1]; ce[0] = pr_[-P + 1];
            const float* h1c = ph1[hp];
            cur[4] = h1c[0];                 // y(t) row 12 (halo)
            s4     = ph0[hp][0];             // y(t) row 13
            cw[4]  = h1c[-1]; ce[4] = h1c[1];
        } else {
            cur[0] = pr_[-P];
            c0n    = pr_[-2 * P];
            cw[0]  = pr_[-P - 1]; ce[0] = pr_[-P + 1];
            cur[4] = pr_[3 * P];
            s4     = pr_[4 * P];
            cw[4]  = pr_[3 * P - 1]; ce[4] = pr_[3 * P + 1];
        }
#pragma unroll
        for (int j = 1; j < 4; ++j) {
            cw[j] = pr_[(j - 1) * P - 1];
            ce[j] = pr_[(j - 1) * P + 1];
        }

        v[0] = fmaf(Qp[0], cur[0],
               fmaf(-Qm[0], prev[0], Rc[0] * ((c0n + cur[1]) + (cw[0] + ce[0]))));
        if (topR && !hasExt) v[0] = 0.f;
#pragma unroll
        for (int j = 1; j < 4; ++j) {
            float yn = fmaf(Qp[j], cur[j],
                       fmaf(-Qm[j], prev[j], Rc[j] * ((cur[j - 1] + cur[j + 1]) + (cw[j] + ce[j]))));
            if (j == 2) {
                if (isSrc) yn += xs1;
                if (isPrb) pacc = fmaf(yn, yn, pacc);
            }
            v[j] = yn;
            pm_[(j - 1) * P] = yn;
        }
        v[4] = fmaf(Qp[4], cur[4],
               fmaf(-Qm[4], prev[4], Rc[4] * ((cur[3] + s4) + (cw[4] + ce[4]))));
        if (botR && !hasExt) v[4] = 0.f;

        rgrp_bar(rgrp + 1);   // orders step-1 pm writes within this rgrp

        // ============ step 2: t+1 -> t+2, own rows j=1..3 ============
        float w2[4], e2[4];
#pragma unroll
        for (int j = 1; j < 4; ++j) {
            w2[j] = pm_[(j - 1) * P - 1];
            e2[j] = pm_[(j - 1) * P + 1];
        }
        auto s2 = [&](int j) -> float {
            float yn = fmaf(Qp[j], v[j],
                       fmaf(-Qm[j], cur[j], Rc[j] * ((v[j - 1] + v[j + 1]) + (w2[j] + e2[j]))));
            if (j == 2) {
                if (isSrc) yn += xs2;
                if (isPrb) pacc = fmaf(yn, yn, pacc);
            }
            po_[(j - 1) * P] = yn;
            prev[j] = v[j];
            cur[j]  = yn;
            return yn;
        };

        if (topR) {
            float a0 = s2(1), a1 = s2(2);        // rows 0, 1
            if (hasExt) {
                st_async_f32(pa1[hq], a0, rmb[hq]);   // row 0 -> nbr row 12 slot
                st_async_f32(pa0[hq], a1, rmb[hq]);   // row 1 -> nbr row 13 slot
            }
            s2(3);
        } else if (botR) {
            float a0 = s2(3), a1 = s2(2);        // rows 11, 10
            if (hasExt) {
                st_async_f32(pa1[hq], a0, rmb[hq]);   // row 11 -> nbr row -1 slot
                st_async_f32(pa0[hq], a1, rmb[hq]);   // row 10 -> nbr row -2 slot
            }
            s2(1);
        } else {
            s2(1); s2(2); s2(3);
        }
        prev[0] = v[0]; prev[4] = v[4];   // seam/ext y(t+1) -> next block's y2

        __syncthreads();   // po (and pm) seam rows visible CTA-wide for next block

        float* t0 = pr_; pr_ = po_; po_ = pm_; pm_ = t0;
    }

    cl_arrive(); cl_wait();   // quiesce in-flight async stores before exit

    if (isPrb) pbuf[(col - 48) / 48] = pacc;
    __syncthreads();
    if (rank == 13 && tid == 0) {
        float a = pbuf[0], b = pbuf[1], c = pbuf[2];
        float s = a + b + c;
        out[batch * 3 + 0] = a / s;
        out[batch * 3 + 1] = b / s;
        out[batch * 3 + 2] = c / s;
    }
}

extern "C" void kernel_launch(void* const* d_in, const int* in_sizes, int n_in,
                              void* d_out, int out_size)
{
    (void)in_sizes; (void)n_in; (void)out_size;
    const float* x   = (const float*)d_in[0];   // (4,256) f32
    const float* rho = (const float*)d_in[1];   // (192,192) f32
    float* out = (float*)d_out;                 // (4,3) f32

    cudaFuncSetAttribute(wave_kernel,
                         cudaFuncAttributeNonPortableClusterSizeAllowed, 1);

    cudaLaunchConfig_t cfg = {};
    cfg.gridDim  = dim3(CS * 4, 1, 1);
    cfg.blockDim = dim3(NTHR, 1, 1);
    cfg.dynamicSmemBytes = 0;
    cudaLaunchAttribute attrs[1];
    attrs[0].id = cudaLaunchAttributeClusterDimension;
    attrs[0].val.clusterDim = {CS, 1, 1};
    cfg.attrs = attrs;
    cfg.numAttrs = 1;
    cudaLaunchKernelEx(&cfg, wave_kernel, x, rho, out);
}

// round 17
// speedup vs baseline: 2.1352x; 1.1193x over previous
#include <cuda_runtime.h>
#include <cstdint>
#include <math.h>

#define CS     16
#define NG     192
#define P      196               // row pitch (2 guard + 192 + 2 guard)
#define FROWS  12                // rows per CTA
#define NTHR   384
#define TSTEPS 256
#define NBLK   (TSTEPS / 2)
#define TXBYTES 1536             // 192 cols x 2 rows x 4B per side per block

typedef unsigned long long ull;

__device__ __forceinline__ uint32_t s2u(const void* p) {
    return (uint32_t)__cvta_generic_to_shared((void*)p);
}
__device__ __forceinline__ uint32_t mapa_u32(uint32_t a, uint32_t r) {
    uint32_t d;
    asm("mapa.shared::cluster.u32 %0, %1, %2;" : "=r"(d) : "r"(a), "r"(r));
    return d;
}
__device__ __forceinline__ void st_async_f32(uint32_t raddr, float v, uint32_t rmbar) {
    asm volatile("st.async.shared::cluster.mbarrier::complete_tx::bytes.b32 [%0], %1, [%2];"
                 :: "r"(raddr), "r"(__float_as_uint(v)), "r"(rmbar) : "memory");
}
__device__ __forceinline__ void mbar_init(uint32_t a, uint32_t cnt) {
    asm volatile("mbarrier.init.shared.b64 [%0], %1;" :: "r"(a), "r"(cnt) : "memory");
}
__device__ __forceinline__ void mbar_expect_tx(uint32_t a, uint32_t bytes) {
    asm volatile("mbarrier.arrive.expect_tx.shared.b64 _, [%0], %1;"
                 :: "r"(a), "r"(bytes) : "memory");
}
__device__ __forceinline__ void mbar_wait(uint32_t addr, uint32_t parity) {
    asm volatile(
        "{\n\t"
        ".reg .pred P;\n\t"
        "WL_%=:\n\t"
        "mbarrier.try_wait.parity.acquire.cta.shared::cta.b64 P, [%0], %1, 0x989680;\n\t"
        "@P bra.uni WD_%=;\n\t"
        "bra.uni WL_%=;\n\t"
        "WD_%=:\n\t"
        "}"
        :: "r"(addr), "r"(parity) : "memory");
}
__device__ __forceinline__ void cl_arrive() {
    asm volatile("barrier.cluster.arrive.aligned;" ::: "memory");
}
__device__ __forceinline__ void cl_wait() {
    asm volatile("barrier.cluster.wait.aligned;" ::: "memory");
}
__device__ __forceinline__ void rgrp_bar(int id) {
    asm volatile("bar.sync %0, %1;" :: "r"(id), "r"(192) : "memory");
}

__device__ __forceinline__ float pml1(int i) {
    int d;
    if (i <= 20)           d = 20 - i;
    else if (i >= NG - 21) d = i - (NG - 21);
    else return 0.0f;
    double t = (double)d * 0.05;
    double t2 = t * t;
    return (float)(3.0 * t2 * t2);
}

__global__ void __launch_bounds__(NTHR, 1)
wave_kernel(const float* __restrict__ x, const float* __restrict__ rho,
            float* __restrict__ out)
{
    __shared__ float bufA[FROWS * P], bufB[FROWS * P], bufC[FROWS * P];
    __shared__ float halo[2][2][2][P];   // [parity][side 0=top,1=bot][0=row∓1,1=row∓2][P]
    __shared__ float xs[TSTEPS];
    __shared__ float pbuf[3];
    __shared__ alignas(8) ull mbarT[2], mbarB[2];

    const int tid   = threadIdx.x;
    const int col   = tid % NG;
    const int rgrp  = tid / NG;           // 0: rows 0..5 (+ext -1), 1: rows 6..11 (+ext 12)
    const int rank  = blockIdx.x % CS;
    const int batch = blockIdx.x / CS;

    for (int i = tid; i < FROWS * P; i += NTHR) { bufA[i] = 0.f; bufB[i] = 0.f; bufC[i] = 0.f; }
    for (int i = tid; i < 2*2*2*P; i += NTHR) (&halo[0][0][0][0])[i] = 0.f;
    for (int i = tid; i < TSTEPS; i += NTHR) xs[i] = x[batch * TSTEPS + i];

    const bool topR = (rgrp == 0);
    const bool hasExt = topR ? (rank > 0) : (rank < CS - 1);

    if (tid == 0) {
#pragma unroll
        for (int p = 0; p < 2; ++p) {
            mbar_init(s2u(&mbarT[p]), 1);
            mbar_init(s2u(&mbarB[p]), 1);
            if (rank > 0)      mbar_expect_tx(s2u(&mbarT[p]), TXBYTES);
            if (rank < CS - 1) mbar_expect_tx(s2u(&mbarB[p]), TXBYTES);
        }
    }

    // ---- coefficients for 8 stencil rows: j=0..7 <-> local row 6*rgrp + j - 1 ----
    const float HM2 = (float)(1.0 / (2.01 * 2.01));
    float Qp[8], Qm[8], Rc[8];
    float cur[8], prev[8], v[8];
#pragma unroll
    for (int j = 0; j < 8; ++j) {
        int g = rank * FROWS + rgrp * 6 + j - 1;
        int gc = min(max(g, 0), NG - 1);
        float cc = rho[gc * NG + col];
        float nn = (gc > 0)      ? rho[(gc - 1) * NG + col] : 0.f;
        float ss = (gc < NG - 1) ? rho[(gc + 1) * NG + col] : 0.f;
        float ww = (col > 0)     ? rho[gc * NG + col - 1]   : 0.f;
        float ee = (col < NG-1)  ? rho[gc * NG + col + 1]   : 0.f;
        float lpf = 0.5f * cc + 0.125f * (nn + ss + ww + ee);
        float pr  = (1.0f + tanhf(100.0f * (lpf - 0.5f))) * 0.5f;
        float c   = 1.0f - 0.1f * pr;
        float bx = pml1(gc), by = pml1(col);
        float bb = sqrtf(bx * bx + by * by);
        float A1 = 1.0f / (1.0f + 0.5f * bb);
        float Q  = A1 * (1.0f - 0.5f * bb);
        float R  = A1 * (c * c) * HM2;
        Qp[j] = 1.0f + Q - 4.0f * R;
        Qm[j] = Q;
        Rc[j] = R;
        cur[j] = 0.f; prev[j] = 0.f; v[j] = 0.f;
    }

    const int side = topR ? 0 : 1;
    const float* ph1[2]; const float* ph0[2];
#pragma unroll
    for (int p = 0; p < 2; ++p) {
        ph1[p] = &halo[p][side][0][col + 2];   // y(t) row ∓1
        ph0[p] = &halo[p][side][1][col + 2];   // y(t) row ∓2
    }
    uint32_t pa1[2] = {0,0}, pa0[2] = {0,0}, rmb[2] = {0,0};
    if (hasExt) {
        int nr = topR ? rank - 1 : rank + 1;
        int ts = topR ? 1 : 0;
#pragma unroll
        for (int p = 0; p < 2; ++p) {
            pa1[p] = mapa_u32(s2u(&halo[p][ts][0][col + 2]), (uint32_t)nr);
            pa0[p] = mapa_u32(s2u(&halo[p][ts][1][col + 2]), (uint32_t)nr);
            rmb[p] = mapa_u32(s2u(topR ? &mbarB[p] : &mbarT[p]), (uint32_t)nr);
        }
    }
    const uint32_t mbOwn[2] = { s2u(topR ? &mbarT[0] : &mbarB[0]),
                                s2u(topR ? &mbarT[1] : &mbarB[1]) };

    const int ofs = rgrp * 6 * P + col + 2;
    float* pr_ = bufA + ofs;    // y(t)
    float* pm_ = bufB + ofs;    // y(t+1)
    float* po_ = bufC + ofs;    // y(t+2)

    // Source (40,96): rank3 rgrp0 j=5. Probes (160,{48,96,144}): rank13 rgrp0 j=5.
    const bool isSrc = (rank == 3)  && topR && (col == 96);
    const bool isPrb = (rank == 13) && topR &&
                       ((col == 48) | (col == 96) | (col == 144));
    float pacc = 0.f;

    cl_arrive(); cl_wait();   // zeros + mbar init/expects visible cluster-wide

    for (int b = 0; b < NBLK; ++b) {
        const int hp = b & 1, hq = hp ^ 1;
        const float xs1 = xs[2 * b];
        const float xs2 = xs[2 * b + 1];

        // ============ step 1: t -> t+1 — halo-independent rows FIRST ============
        float cw[8], ce[8];
#pragma unroll
        for (int j = 1; j < 7; ++j) {
            cw[j] = pr_[(j - 1) * P - 1];
            ce[j] = pr_[(j - 1) * P + 1];
        }

        if (topR) {
            // seam side (j=7) is halo-independent
            cur[7]     = pr_[6 * P];
            float s7   = pr_[7 * P];
            cw[7]      = pr_[6 * P - 1];
            ce[7]      = pr_[6 * P + 1];
            // rows j=2..6 (no halo dependency)
#pragma unroll
            for (int j = 2; j < 7; ++j) {
                float yn = fmaf(Qp[j], cur[j],
                           fmaf(-Qm[j], prev[j], Rc[j] * ((cur[j - 1] + cur[j + 1]) + (cw[j] + ce[j]))));
                if (j == 5) {
                    if (isSrc) yn += xs1;
                    if (isPrb) pacc = fmaf(yn, yn, pacc);
                }
                v[j] = yn;
                pm_[(j - 1) * P] = yn;
            }
            v[7] = fmaf(Qp[7], cur[7],
                   fmaf(-Qm[7], prev[7], Rc[7] * ((cur[6] + s7) + (cw[7] + ce[7]))));

            // ---- wait for neighbor's halo (usually already complete) ----
            if (hasExt && b > 0) {
                mbar_wait(mbOwn[hp], (uint32_t)(((b - 1) >> 1) & 1));
                if (col == 0) mbar_expect_tx(mbOwn[hp], TXBYTES);
            }
            // halo-dependent rows j=0,1
            const float* h1c = ph1[hp];
            cur[0]    = h1c[0];              // y(t) row -1
            float c0n = ph0[hp][0];          // y(t) row -2
            cw[0] = h1c[-1]; ce[0] = h1c[1];
            v[0] = fmaf(Qp[0], cur[0],
                   fmaf(-Qm[0], prev[0], Rc[0] * ((c0n + cur[1]) + (cw[0] + ce[0]))));
            if (!hasExt) v[0] = 0.f;
            {
                float yn = fmaf(Qp[1], cur[1],
                           fmaf(-Qm[1], prev[1], Rc[1] * ((cur[0] + cur[2]) + (cw[1] + ce[1]))));
                v[1] = yn;
                pm_[0] = yn;
            }
        } else {
            // seam side (j=0) is halo-independent
            cur[0]     = pr_[-P];            // seam row 5
            float c0n  = pr_[-2 * P];        // row 4
            cw[0]      = pr_[-P - 1];
            ce[0]      = pr_[-P + 1];
            v[0] = fmaf(Qp[0], cur[0],
                   fmaf(-Qm[0], prev[0], Rc[0] * ((c0n + cur[1]) + (cw[0] + ce[0]))));
            // rows j=1..5 (no halo dependency)
#pragma unroll
            for (int j = 1; j < 6; ++j) {
                float yn = fmaf(Qp[j], cur[j],
                           fmaf(-Qm[j], prev[j], Rc[j] * ((cur[j - 1] + cur[j + 1]) + (cw[j] + ce[j]))));
                v[j] = yn;
                pm_[(j - 1) * P] = yn;
            }

            // ---- wait for neighbor's halo ----
            if (hasExt && b > 0) {
                mbar_wait(mbOwn[hp], (uint32_t)(((b - 1) >> 1) & 1));
                if (col == 0) mbar_expect_tx(mbOwn[hp], TXBYTES);
            }
            // halo-dependent rows j=6,7
            const float* h1c = ph1[hp];
            cur[7]    = h1c[0];              // y(t) row 12
            float s7  = ph0[hp][0];          // y(t) row 13
            cw[7] = h1c[-1]; ce[7] = h1c[1];
            {
                float yn = fmaf(Qp[6], cur[6],
                           fmaf(-Qm[6], prev[6], Rc[6] * ((cur[5] + cur[7]) + (cw[6] + ce[6]))));
                v[6] = yn;
                pm_[5 * P] = yn;
            }
            v[7] = fmaf(Qp[7], cur[7],
                   fmaf(-Qm[7], prev[7], Rc[7] * ((cur[6] + s7) + (cw[7] + ce[7]))));
            if (!hasExt) v[7] = 0.f;
        }

        rgrp_bar(rgrp + 1);   // orders step-1 pm writes within this rgrp

        // ============ step 2: t+1 -> t+2, own rows j=1..6 ============
        float w2[7], e2[7];
#pragma unroll
        for (int j = 1; j < 7; ++j) {
            w2[j] = pm_[(j - 1) * P - 1];
            e2[j] = pm_[(j - 1) * P + 1];
        }
        auto s2 = [&](int j) -> float {
            float yn = fmaf(Qp[j], v[j],
                       fmaf(-Qm[j], cur[j], Rc[j] * ((v[j - 1] + v[j + 1]) + (w2[j] + e2[j]))));
            if (j == 5) {
                if (isSrc) yn += xs2;
                if (isPrb) pacc = fmaf(yn, yn, pacc);
            }
            po_[(j - 1) * P] = yn;
            prev[j] = v[j];
            cur[j]  = yn;
            return yn;
        };

        if (topR) {
            float a0 = s2(1), a1 = s2(2);       // rows 0, 1
            if (hasExt) {
                st_async_f32(pa1[hq], a0, rmb[hq]);   // y(t+2) row 0  -> nbr row 12 slot
                st_async_f32(pa0[hq], a1, rmb[hq]);   // y(t+2) row 1  -> nbr row 13 slot
            }
        } else {
            float a0 = s2(6), a1 = s2(5);       // rows 11, 10
            if (hasExt) {
                st_async_f32(pa1[hq], a0, rmb[hq]);   // y(t+2) row 11 -> nbr row -1 slot
                st_async_f32(pa0[hq], a1, rmb[hq]);   // y(t+2) row 10 -> nbr row -2 slot
            }
        }

        if (topR) { s2(3); s2(4); s2(5); s2(6); }
        else      { s2(4); s2(3); s2(2); s2(1); }
        prev[0] = v[0]; prev[7] = v[7];

        __syncthreads();   // po visible CTA-wide (seam + W/E reads next block)

        float* t0 = pr_; pr_ = po_; po_ = pm_; pm_ = t0;
    }

    cl_arrive(); cl_wait();   // quiesce in-flight async stores before exit

    if (isPrb) pbuf[(col - 48) / 48] = pacc;
    __syncthreads();
    if (rank == 13 && tid == 0) {
        float a = pbuf[0], b = pbuf[1], c = pbuf[2];
        float s = a + b + c;
        out[batch * 3 + 0] = a / s;
        out[batch * 3 + 1] = b / s;
        out[batch * 3 + 2] = c / s;
    }
}

extern "C" void kernel_launch(void* const* d_in, const int* in_sizes, int n_in,
                              void* d_out, int out_size)
{
    (void)in_sizes; (void)n_in; (void)out_size;
    const float* x   = (const float*)d_in[0];   // (4,256) f32
    const float* rho = (const float*)d_in[1];   // (192,192) f32
    float* out = (float*)d_out;                 // (4,3) f32

    cudaFuncSetAttribute(wave_kernel,
                         cudaFuncAttributeNonPortableClusterSizeAllowed, 1);

    cudaLaunchConfig_t cfg = {};
    cfg.gridDim  = dim3(CS * 4, 1, 1);
    cfg.blockDim = dim3(NTHR, 1, 1);
    cfg.dynamicSmemBytes = 0;
    cudaLaunchAttribute attrs[1];
    attrs[0].id = cudaLaunchAttributeClusterDimension;
    attrs[0].val.clusterDim = {CS, 1, 1};
    cfg.attrs = attrs;
    cfg.numAttrs = 1;
    cudaLaunchKernelEx(&cfg, wave_kernel, x, rho, out);
}